// round 8
// baseline (speedup 1.0000x reference)
#include <cuda_runtime.h>
#include <cuda_fp16.h>
#include <cstdint>
#include <cstddef>

#define TT 64
#define BB 512
#define DD 512
#define HH 2048

// ---------------- scratch (device globals) ---------------------------------
__device__ __align__(16) float  g_ycur[BB * DD];
__device__ __align__(16) float  g_acc [BB * DD];
__device__ __align__(16) __half g_a   [BB * DD];          // gemm1 A operand
__device__ __align__(16) __half g_h   [(size_t)BB * HH];  // hidden activations
__device__ __align__(16) __half g_W1h [(size_t)DD * HH];
__device__ __align__(16) __half g_W2h [(size_t)HH * DD];
__device__ __align__(16) float  g_part[3][BB * DD];       // split-K partials (kz=1..3)
__device__ int g_cnt[32];        // per (rowblock 0..7, quadrant 0..3) gemm1 completion
__device__ int g_flag2[256];     // per (tile 0..63, kz 0..3) split-K flags

// ---------------- ptx helpers ----------------------------------------------
__device__ __forceinline__ uint32_t su32(const void* p) {
    return (uint32_t)__cvta_generic_to_shared(p);
}
#define CPA16(d, s) asm volatile("cp.async.cg.shared.global [%0], [%1], 16;" :: "r"(d), "l"(s))
#define CPC()       asm volatile("cp.async.commit_group;" ::: "memory")
#define WAITG(n)    asm volatile("cp.async.wait_group %0;" :: "n"(n) : "memory")

__device__ __forceinline__ void ldsm_x4(uint32_t a[4], uint32_t addr) {
    asm volatile("ldmatrix.sync.aligned.m8n8.x4.shared.b16 {%0,%1,%2,%3}, [%4];"
                 : "=r"(a[0]), "=r"(a[1]), "=r"(a[2]), "=r"(a[3]) : "r"(addr));
}
__device__ __forceinline__ void ldsm_x4_t(uint32_t a[4], uint32_t addr) {
    asm volatile("ldmatrix.sync.aligned.m8n8.x4.trans.shared.b16 {%0,%1,%2,%3}, [%4];"
                 : "=r"(a[0]), "=r"(a[1]), "=r"(a[2]), "=r"(a[3]) : "r"(addr));
}
__device__ __forceinline__ void mma_fp16(float c[4], const uint32_t a[4],
                                         uint32_t b0, uint32_t b1) {
    asm volatile(
        "mma.sync.aligned.m16n8k16.row.col.f32.f16.f16.f32 "
        "{%0,%1,%2,%3},{%4,%5,%6,%7},{%8,%9},{%0,%1,%2,%3};"
        : "+f"(c[0]), "+f"(c[1]), "+f"(c[2]), "+f"(c[3])
        : "r"(a[0]), "r"(a[1]), "r"(a[2]), "r"(a[3]), "r"(b0), "r"(b1));
}

// ---------------- init / convert -------------------------------------------
__global__ void init_state(const float* __restrict__ y0, float* __restrict__ out) {
    int idx = blockIdx.x * blockDim.x + threadIdx.x;
    float4 v = ((const float4*)y0)[idx];
    ((float4*)out)[idx] = v;
    ((float4*)g_ycur)[idx] = v;
    __half2* a2 = (__half2*)g_a;
    a2[idx * 2]     = __floats2half2_rn(v.x, v.y);
    a2[idx * 2 + 1] = __floats2half2_rn(v.z, v.w);
    if (blockIdx.x == 0) {
        if (threadIdx.x < 32)  g_cnt[threadIdx.x] = 0;
        if (threadIdx.x < 256) g_flag2[threadIdx.x] = 0;
    }
}
__global__ void convert_w(const float* __restrict__ src, __half* __restrict__ dst) {
    int idx = blockIdx.x * blockDim.x + threadIdx.x;
    float4 v = ((const float4*)src)[idx];
    __half2* d2 = (__half2*)dst;
    d2[idx * 2]     = __floats2half2_rn(v.x, v.y);
    d2[idx * 2 + 1] = __floats2half2_rn(v.z, v.w);
}

extern __shared__ char dyn_sm[];

// ============================================================================
// 64x64 GEMM tile: acc[2][2][4] = A[64 x 512] @ B[512 x 64]
// 256 thr, warps 2x4 (warp tile 32x16), BK=64, 4-stage cp.async,
// register-double-buffered fragments. NT = 8 k-tiles.
// ============================================================================
#define APIT 72                         // smem pitch (halves)
#define ABY  (64 * APIT * 2)            // 9216 B
#define STG  (2 * ABY)                  // 18432 B per stage
#define SMEMB (4 * STG)                 // 73728 B

template<int LDAg, int LDBg>
__device__ __forceinline__ void gemm_tile(const __half* __restrict__ Ag,
                                          const __half* __restrict__ Bg,
                                          float acc[2][2][4]) {
    const int tid = threadIdx.x, lane = tid & 31, warp = tid >> 5;
    const int wm = (warp >> 2) * 32, wn = (warp & 3) * 16;
    const int l16 = lane & 15, h16 = (lane >> 4) * 8;

    auto loadStage = [&](int st, int kt) {
        char* Ab = dyn_sm + st * STG;
        char* Bb = Ab + ABY;
#pragma unroll
        for (int l = 0; l < 2; l++) {
            int j = tid + l * 256, r = j >> 3, c = (j & 7) * 8;
            CPA16(su32(Ab + (r * APIT + c) * 2), Ag + (size_t)r * LDAg + kt * 64 + c);
        }
#pragma unroll
        for (int l = 0; l < 2; l++) {
            int j = tid + l * 256, r = j >> 3, c = (j & 7) * 8;
            CPA16(su32(Bb + (r * APIT + c) * 2), Bg + (size_t)(kt * 64 + r) * LDBg + c);
        }
        CPC();
    };
    auto ldfA = [&](uint32_t Af[2][4], int st, int ks) {
        char* Ab = dyn_sm + st * STG;
#pragma unroll
        for (int mi = 0; mi < 2; mi++)
            ldsm_x4(Af[mi], su32(Ab + ((wm + mi * 16 + l16) * APIT + ks + h16) * 2));
    };
    auto ldfB = [&](uint32_t Bf[2][2], int st, int ks) {
        char* Bb = dyn_sm + st * STG + ABY;
        uint32_t r[4];
        ldsm_x4_t(r, su32(Bb + ((ks + l16) * APIT + wn + h16) * 2));
        Bf[0][0] = r[0]; Bf[0][1] = r[1];
        Bf[1][0] = r[2]; Bf[1][1] = r[3];
    };

    loadStage(0, 0); loadStage(1, 1); loadStage(2, 2);
    WAITG(2);
    __syncthreads();

#pragma unroll
    for (int mi = 0; mi < 2; mi++)
#pragma unroll
        for (int ni = 0; ni < 2; ni++)
#pragma unroll
            for (int r = 0; r < 4; r++) acc[mi][ni][r] = 0.f;

    uint32_t Af[2][2][4], Bf[2][2][2];
    ldfA(Af[0], 0, 0); ldfB(Bf[0], 0, 0);

    for (int kt = 0; kt < 8; kt++) {
        const int st = kt & 3;
#pragma unroll
        for (int ks = 0; ks < 4; ks++) {
            const int pb = ks & 1;
            if (ks == 3) { WAITG(1); __syncthreads(); }
            const int nst = (ks < 3) ? st : ((kt + 1) & 3);
            const int nks = (ks < 3) ? (ks + 1) * 16 : 0;
            if (ks < 3 || kt + 1 < 8) {
                ldfA(Af[pb ^ 1], nst, nks);
                ldfB(Bf[pb ^ 1], nst, nks);
            }
#pragma unroll
            for (int mi = 0; mi < 2; mi++)
#pragma unroll
                for (int ni = 0; ni < 2; ni++)
                    mma_fp16(acc[mi][ni], Af[pb][mi], Bf[pb][ni][0], Bf[pb][ni][1]);
        }
        if (kt + 3 < 8) loadStage((kt + 3) & 3, kt + 3); else CPC();
    }
}

// ============================================================================
// Fused RK substage: phase 1 (gemm1 tile) -> counters -> phase 2 (gemm2 tile,
// split-K=4, flag reduction, RK4 epilogue).  Grid = 256 CTAs, MUST be fully
// co-resident (occupancy 2: smem 73728 <= 113KB, regs capped at 128).
// ============================================================================
__global__ void __launch_bounds__(256, 2) stage_kernel(const float* __restrict__ b1,
                                                       const float* __restrict__ b2,
                                                       const float* __restrict__ tarr,
                                                       float* __restrict__ out,
                                                       int s, float wgt, float cnext,
                                                       int first, int last, int need) {
    const int id = blockIdx.x;
    const int tid = threadIdx.x, lane = tid & 31, warp = tid >> 5;
    const int g = lane >> 2, tg = lane & 3;
    const int wm = (warp >> 2) * 32, wn = (warp & 3) * 16;

    // ---------------- phase 1: g_h tile = tanh(g_a @ W1 + b1) --------------
    {
        const int bm = (id >> 5) * 64, bn = (id & 31) * 64;
        float acc[2][2][4];
        gemm_tile<DD, HH>(g_a + (size_t)bm * DD, g_W1h + bn, acc);

#pragma unroll
        for (int mi = 0; mi < 2; mi++)
#pragma unroll
            for (int ni = 0; ni < 2; ni++) {
                int col = bn + wn + ni * 8 + tg * 2;
                float bc0 = __ldg(b1 + col), bc1 = __ldg(b1 + col + 1);
#pragma unroll
                for (int hr = 0; hr < 2; hr++) {
                    int row = bm + wm + mi * 16 + g + hr * 8;
                    float v0 = tanhf(acc[mi][ni][hr * 2 + 0] + bc0);
                    float v1 = tanhf(acc[mi][ni][hr * 2 + 1] + bc1);
                    *(__half2*)&g_h[(size_t)row * HH + col] = __floats2half2_rn(v0, v1);
                }
            }
        __syncthreads();
        if (tid == 0) {
            __threadfence();
            atomicAdd(&g_cnt[(id >> 5) * 4 + ((id & 31) >> 3)], 1);
        }
    }

    // ---------------- phase 2: gemm2 tile (split-K) ------------------------
    const int kz = id & 3, tile = id >> 2;
    const int bm = (tile >> 3) * 64, bn = (tile & 7) * 64;

    if (tid == 0) {
        while (atomicAdd(&g_cnt[(bm >> 6) * 4 + kz], 0) < need) __nanosleep(64);
        __threadfence();
    }
    __syncthreads();

    float acc[2][2][4];
    gemm_tile<HH, DD>(g_h + (size_t)bm * HH + kz * 512,
                      g_W2h + (size_t)(kz * 512) * DD + bn, acc);

    if (kz != 0) {
        float* dst = g_part[kz - 1];
#pragma unroll
        for (int mi = 0; mi < 2; mi++)
#pragma unroll
            for (int ni = 0; ni < 2; ni++)
#pragma unroll
                for (int r = 0; r < 4; r++) {
                    int row = bm + wm + mi * 16 + g + ((r >= 2) ? 8 : 0);
                    int col = bn + wn + ni * 8 + tg * 2 + (r & 1);
                    dst[(size_t)row * DD + col] = acc[mi][ni][r];
                }
        __syncthreads();
        if (tid == 0) {
            __threadfence();
            atomicExch(&g_flag2[tile * 4 + kz], 1);
        }
        return;
    }

    // kz == 0: collect peers, combine, RK4 epilogue
    if (tid == 0) {
#pragma unroll
        for (int j = 1; j < 4; j++)
            while (atomicCAS(&g_flag2[tile * 4 + j], 1, 0) != 1) __nanosleep(64);
        __threadfence();
    }
    __syncthreads();

    const float inv6 = 1.0f / 6.0f;
#pragma unroll
    for (int mi = 0; mi < 2; mi++) {
#pragma unroll
        for (int hr = 0; hr < 2; hr++) {
            int row = bm + wm + mi * 16 + g + hr * 8;
            float dt = __ldg(tarr + (size_t)(s + 1) * BB + row)
                     - __ldg(tarr + (size_t)s * BB + row);
#pragma unroll
            for (int ni = 0; ni < 2; ni++) {
#pragma unroll
                for (int q = 0; q < 2; q++) {
                    int r = hr * 2 + q;
                    int col = bn + wn + ni * 8 + tg * 2 + q;
                    size_t off = (size_t)row * DD + col;
                    float sum = acc[mi][ni][r] + g_part[0][off] + g_part[1][off]
                              + g_part[2][off];
                    float knew = dt * (sum + __ldg(b2 + col));
                    float a = first ? (wgt * knew) : (g_acc[off] + wgt * knew);
                    if (!last) {
                        g_acc[off] = a;
                        g_a[off] = __float2half(g_ycur[off] + cnext * knew);
                    } else {
                        float yn = g_ycur[off] + a * inv6;
                        g_ycur[off] = yn;
                        out[(size_t)(s + 1) * BB * DD + off] = yn;
                        g_a[off] = __float2half(yn);
                    }
                }
            }
        }
    }
}

// ---------------------------------------------------------------------------
extern "C" void kernel_launch(void* const* d_in, const int* in_sizes, int n_in,
                              void* d_out, int out_size) {
    const float* y0 = (const float*)d_in[0];
    const float* t  = (const float*)d_in[1];
    const float* W1 = (const float*)d_in[2];
    const float* b1 = (const float*)d_in[3];
    const float* W2 = (const float*)d_in[4];
    const float* b2 = (const float*)d_in[5];
    float* out = (float*)d_out;

    cudaFuncSetAttribute(stage_kernel, cudaFuncAttributeMaxDynamicSharedMemorySize, SMEMB);

    __half* w1h; cudaGetSymbolAddress((void**)&w1h, g_W1h);
    __half* w2h; cudaGetSymbolAddress((void**)&w2h, g_W2h);

    init_state<<<(BB * DD / 4) / 256, 256>>>(y0, out);
    convert_w<<<(DD * HH / 4) / 256, 256>>>(W1, w1h);
    convert_w<<<(HH * DD / 4) / 256, 256>>>(W2, w2h);

    const float ws[4] = {1.0f, 2.0f, 2.0f, 1.0f};
    const float cn[4] = {0.5f, 0.5f, 1.0f, 0.0f};

    for (int s = 0; s < TT - 1; ++s) {
        for (int i = 0; i < 4; ++i) {
            int gen = s * 4 + i + 1;
            stage_kernel<<<256, 256, SMEMB>>>(b1, b2, t, out, s, ws[i], cn[i],
                                              (i == 0) ? 1 : 0, (i == 3) ? 1 : 0,
                                              8 * gen);
        }
    }
}

// round 9
// speedup vs baseline: 1.2819x; 1.2819x over previous
#include <cuda_runtime.h>
#include <cuda_fp16.h>
#include <cstdint>
#include <cstddef>

#define TT 64
#define BB 512
#define DD 512
#define HH 2048

// ---------------- scratch (device globals) ---------------------------------
__device__ __align__(16) float  g_ycur[BB * DD];
__device__ __align__(16) float  g_acc [BB * DD];
__device__ __align__(16) __half g_a   [BB * DD];          // gemm1 A operand
__device__ __align__(16) __half g_h   [(size_t)BB * HH];  // hidden activations
__device__ __align__(16) __half g_W1h [(size_t)DD * HH];
__device__ __align__(16) __half g_W2h [(size_t)HH * DD];
__device__ __align__(16) float  g_part[3][BB * DD];       // split-K partials (kz=1..3)
__device__ int g_flag2[512];     // per (tile 0..127, kz 0..3) split-K flags

// ---------------- ptx helpers ----------------------------------------------
__device__ __forceinline__ uint32_t su32(const void* p) {
    return (uint32_t)__cvta_generic_to_shared(p);
}
#define CPA16(d, s) asm volatile("cp.async.cg.shared.global [%0], [%1], 16;" :: "r"(d), "l"(s))
#define CPC()       asm volatile("cp.async.commit_group;" ::: "memory")
#define WAITG(n)    asm volatile("cp.async.wait_group %0;" :: "n"(n) : "memory")

__device__ __forceinline__ void ldsm_x4(uint32_t a[4], uint32_t addr) {
    asm volatile("ldmatrix.sync.aligned.m8n8.x4.shared.b16 {%0,%1,%2,%3}, [%4];"
                 : "=r"(a[0]), "=r"(a[1]), "=r"(a[2]), "=r"(a[3]) : "r"(addr));
}
__device__ __forceinline__ void ldsm_x4_t(uint32_t a[4], uint32_t addr) {
    asm volatile("ldmatrix.sync.aligned.m8n8.x4.trans.shared.b16 {%0,%1,%2,%3}, [%4];"
                 : "=r"(a[0]), "=r"(a[1]), "=r"(a[2]), "=r"(a[3]) : "r"(addr));
}
__device__ __forceinline__ void mma_fp16(float c[4], const uint32_t a[4],
                                         uint32_t b0, uint32_t b1) {
    asm volatile(
        "mma.sync.aligned.m16n8k16.row.col.f32.f16.f16.f32 "
        "{%0,%1,%2,%3},{%4,%5,%6,%7},{%8,%9},{%0,%1,%2,%3};"
        : "+f"(c[0]), "+f"(c[1]), "+f"(c[2]), "+f"(c[3])
        : "r"(a[0]), "r"(a[1]), "r"(a[2]), "r"(a[3]), "r"(b0), "r"(b1));
}

// ---------------- init / convert -------------------------------------------
__global__ void init_state(const float* __restrict__ y0, float* __restrict__ out) {
    int idx = blockIdx.x * blockDim.x + threadIdx.x;
    float4 v = ((const float4*)y0)[idx];
    ((float4*)out)[idx] = v;
    ((float4*)g_ycur)[idx] = v;
    __half2* a2 = (__half2*)g_a;
    a2[idx * 2]     = __floats2half2_rn(v.x, v.y);
    a2[idx * 2 + 1] = __floats2half2_rn(v.z, v.w);
    if (blockIdx.x == 0 && threadIdx.x < 256) {
        g_flag2[threadIdx.x] = 0;
        g_flag2[threadIdx.x + 256] = 0;
    }
}
__global__ void convert_w(const float* __restrict__ src, __half* __restrict__ dst) {
    int idx = blockIdx.x * blockDim.x + threadIdx.x;
    float4 v = ((const float4*)src)[idx];
    __half2* d2 = (__half2*)dst;
    d2[idx * 2]     = __floats2half2_rn(v.x, v.y);
    d2[idx * 2 + 1] = __floats2half2_rn(v.z, v.w);
}

extern __shared__ char dyn_sm[];

// ============================================================================
// 32x64 GEMM tile, K=512: acc[4][4] = A[32 x 512] @ B[512 x 64]
// 128 thr, 4 warps as 2m x 2n (warp tile 16x32), BK=64, NT=8, 3-stage
// cp.async, register-double-buffered fragments.
// ============================================================================
#define APIT 72                         // smem pitch (halves)
#define ABY  (32 * APIT * 2)            // 4608 B
#define BBY  (64 * APIT * 2)            // 9216 B
#define STG  (ABY + BBY)                // 13824 B per stage
#define SMEMB (3 * STG)                 // 41472 B

template<int LDAg, int LDBg>
__device__ __forceinline__ void gemm_tile(const __half* __restrict__ Ag,
                                          const __half* __restrict__ Bg,
                                          float acc[4][4]) {
    const int tid = threadIdx.x, lane = tid & 31, warp = tid >> 5;
    const int wm = (warp >> 1) * 16, wn = (warp & 1) * 32;
    const int l16 = lane & 15, h16 = (lane >> 4) * 8;

    auto loadStage = [&](int st, int kt) {
        char* Ab = dyn_sm + st * STG;
        char* Bb = Ab + ABY;
#pragma unroll
        for (int l = 0; l < 2; l++) {
            int j = tid + l * 128, r = j >> 3, c = (j & 7) * 8;
            CPA16(su32(Ab + (r * APIT + c) * 2), Ag + (size_t)r * LDAg + kt * 64 + c);
        }
#pragma unroll
        for (int l = 0; l < 4; l++) {
            int j = tid + l * 128, r = j >> 3, c = (j & 7) * 8;
            CPA16(su32(Bb + (r * APIT + c) * 2), Bg + (size_t)(kt * 64 + r) * LDBg + c);
        }
        CPC();
    };
    auto ldfA = [&](uint32_t Af[4], int st, int ks) {
        char* Ab = dyn_sm + st * STG;
        ldsm_x4(Af, su32(Ab + ((wm + l16) * APIT + ks + h16) * 2));
    };
    auto ldfB = [&](uint32_t Bf[4][2], int st, int ks) {
        char* Bb = dyn_sm + st * STG + ABY;
#pragma unroll
        for (int bt = 0; bt < 2; bt++) {
            uint32_t r[4];
            ldsm_x4_t(r, su32(Bb + ((ks + l16) * APIT + wn + bt * 16 + h16) * 2));
            Bf[bt * 2][0] = r[0]; Bf[bt * 2][1] = r[1];
            Bf[bt * 2 + 1][0] = r[2]; Bf[bt * 2 + 1][1] = r[3];
        }
    };

    loadStage(0, 0); loadStage(1, 1); loadStage(2, 2);
    WAITG(2);
    __syncthreads();

#pragma unroll
    for (int ni = 0; ni < 4; ni++)
#pragma unroll
        for (int r = 0; r < 4; r++) acc[ni][r] = 0.f;

    uint32_t Af[2][4], Bf[2][4][2];
    ldfA(Af[0], 0, 0); ldfB(Bf[0], 0, 0);

    for (int kt = 0; kt < 8; kt++) {
        const int st = kt % 3;
#pragma unroll
        for (int ks = 0; ks < 4; ks++) {
            const int pb = ks & 1;
            if (ks == 3) { WAITG(1); __syncthreads(); }
            const int nst = (ks < 3) ? st : ((kt + 1) % 3);
            const int nks = (ks < 3) ? (ks + 1) * 16 : 0;
            if (ks < 3 || kt + 1 < 8) {
                ldfA(Af[pb ^ 1], nst, nks);
                ldfB(Bf[pb ^ 1], nst, nks);
            }
#pragma unroll
            for (int ni = 0; ni < 4; ni++)
                mma_fp16(acc[ni], Af[pb], Bf[pb][ni][0], Bf[pb][ni][1]);
        }
        if (kt + 3 < 8) loadStage((kt + 3) % 3, kt + 3); else CPC();
    }
}

// ============================================================================
// GEMM1: g_h = tanh(g_a[512x512] @ W1[512x2048] + b1).  Grid (32, 16) = 512.
// ============================================================================
__global__ void __launch_bounds__(128, 4) gemm1_kernel(const float* __restrict__ b1) {
    const int bm = blockIdx.y * 32, bn = blockIdx.x * 64;
    const int lane = threadIdx.x & 31, warp = threadIdx.x >> 5;
    const int g = lane >> 2, tg = lane & 3;
    const int wm = (warp >> 1) * 16, wn = (warp & 1) * 32;

    float acc[4][4];
    gemm_tile<DD, HH>(g_a + (size_t)bm * DD, g_W1h + bn, acc);

#pragma unroll
    for (int ni = 0; ni < 4; ni++) {
        int col = bn + wn + ni * 8 + tg * 2;
        float bc0 = __ldg(b1 + col), bc1 = __ldg(b1 + col + 1);
#pragma unroll
        for (int hr = 0; hr < 2; hr++) {
            int row = bm + wm + g + hr * 8;
            float v0 = tanhf(acc[ni][hr * 2 + 0] + bc0);
            float v1 = tanhf(acc[ni][hr * 2 + 1] + bc1);
            *(__half2*)&g_h[(size_t)row * HH + col] = __floats2half2_rn(v0, v1);
        }
    }
}

// ============================================================================
// GEMM2: C = g_h[512x2048] @ W2[2048x512], split-K=4 (kz = blockIdx.z, K=512
// each).  Grid (8, 16, 4) = 512 CTAs.  kz=1..3 publish partials + flags;
// kz=0 collects (deterministic fixed-order sum) + RK4 epilogue.
// Co-residency of all 512 CTAs guaranteed: smem 41472*4 <= 227KB, regs <= 128.
// ============================================================================
__global__ void __launch_bounds__(128, 4) gemm2_kernel(const float* __restrict__ b2,
                                                       const float* __restrict__ tarr,
                                                       float* __restrict__ out,
                                                       int s, float wgt, float cnext,
                                                       int first, int last) {
    const int bm = blockIdx.y * 32, bn = blockIdx.x * 64;
    const int kz = blockIdx.z;
    const int tile = blockIdx.y * 8 + blockIdx.x;
    const int tid = threadIdx.x, lane = tid & 31, warp = tid >> 5;
    const int g = lane >> 2, tg = lane & 3;
    const int wm = (warp >> 1) * 16, wn = (warp & 1) * 32;

    float acc[4][4];
    gemm_tile<HH, DD>(g_h + (size_t)bm * HH + kz * 512,
                      g_W2h + (size_t)(kz * 512) * DD + bn, acc);

    if (kz != 0) {
        float* dst = g_part[kz - 1];
#pragma unroll
        for (int ni = 0; ni < 4; ni++) {
            int col = bn + wn + ni * 8 + tg * 2;
#pragma unroll
            for (int hr = 0; hr < 2; hr++) {
                int row = bm + wm + g + hr * 8;
                *(float2*)&dst[(size_t)row * DD + col] =
                    make_float2(acc[ni][hr * 2 + 0], acc[ni][hr * 2 + 1]);
            }
        }
        __syncthreads();
        if (tid == 0) {
            __threadfence();
            atomicExch(&g_flag2[tile * 4 + kz], 1);
        }
        return;
    }

    // kz == 0: collect peers (reset flags for next replay), combine, epilogue
    if (tid == 0) {
#pragma unroll
        for (int j = 1; j < 4; j++)
            while (atomicCAS(&g_flag2[tile * 4 + j], 1, 0) != 1) __nanosleep(64);
        __threadfence();
    }
    __syncthreads();

    const float inv6 = 1.0f / 6.0f;
#pragma unroll
    for (int hr = 0; hr < 2; hr++) {
        int row = bm + wm + g + hr * 8;
        float dt = __ldg(tarr + (size_t)(s + 1) * BB + row)
                 - __ldg(tarr + (size_t)s * BB + row);
#pragma unroll
        for (int ni = 0; ni < 4; ni++) {
            int col = bn + wn + ni * 8 + tg * 2;
            size_t off = (size_t)row * DD + col;
            float2 p0 = *(const float2*)&g_part[0][off];
            float2 p1 = *(const float2*)&g_part[1][off];
            float2 p2 = *(const float2*)&g_part[2][off];
            float sum0 = acc[ni][hr * 2 + 0] + p0.x + p1.x + p2.x;
            float sum1 = acc[ni][hr * 2 + 1] + p0.y + p1.y + p2.y;
            float k0 = dt * (sum0 + __ldg(b2 + col));
            float k1 = dt * (sum1 + __ldg(b2 + col + 1));
            float2 yc = *(const float2*)&g_ycur[off];
            if (!last) {
                float2 a;
                if (first) { a = make_float2(wgt * k0, wgt * k1); }
                else {
                    float2 p = *(const float2*)&g_acc[off];
                    a = make_float2(p.x + wgt * k0, p.y + wgt * k1);
                }
                *(float2*)&g_acc[off] = a;
                *(__half2*)&g_a[off] =
                    __floats2half2_rn(yc.x + cnext * k0, yc.y + cnext * k1);
            } else {
                float2 p = *(const float2*)&g_acc[off];
                float yn0 = yc.x + (p.x + wgt * k0) * inv6;
                float yn1 = yc.y + (p.y + wgt * k1) * inv6;
                *(float2*)&g_ycur[off] = make_float2(yn0, yn1);
                *(float2*)&out[(size_t)(s + 1) * BB * DD + off] = make_float2(yn0, yn1);
                *(__half2*)&g_a[off] = __floats2half2_rn(yn0, yn1);
            }
        }
    }
}

// ---------------------------------------------------------------------------
extern "C" void kernel_launch(void* const* d_in, const int* in_sizes, int n_in,
                              void* d_out, int out_size) {
    const float* y0 = (const float*)d_in[0];
    const float* t  = (const float*)d_in[1];
    const float* W1 = (const float*)d_in[2];
    const float* b1 = (const float*)d_in[3];
    const float* W2 = (const float*)d_in[4];
    const float* b2 = (const float*)d_in[5];
    float* out = (float*)d_out;

    cudaFuncSetAttribute(gemm1_kernel, cudaFuncAttributeMaxDynamicSharedMemorySize, SMEMB);
    cudaFuncSetAttribute(gemm2_kernel, cudaFuncAttributeMaxDynamicSharedMemorySize, SMEMB);

    __half* w1h; cudaGetSymbolAddress((void**)&w1h, g_W1h);
    __half* w2h; cudaGetSymbolAddress((void**)&w2h, g_W2h);

    init_state<<<(BB * DD / 4) / 256, 256>>>(y0, out);
    convert_w<<<(DD * HH / 4) / 256, 256>>>(W1, w1h);
    convert_w<<<(HH * DD / 4) / 256, 256>>>(W2, w2h);

    const float ws[4] = {1.0f, 2.0f, 2.0f, 1.0f};
    const float cn[4] = {0.5f, 0.5f, 1.0f, 0.0f};

    dim3 grid1(HH / 64, BB / 32);      // 32 x 16 = 512 CTAs
    dim3 grid2(DD / 64, BB / 32, 4);   // 8 x 16 x 4 = 512 CTAs

    for (int s = 0; s < TT - 1; ++s) {
        for (int i = 0; i < 4; ++i) {
            gemm1_kernel<<<grid1, 128, SMEMB>>>(b1);
            gemm2_kernel<<<grid2, 128, SMEMB>>>(b2, t, out, s, ws[i], cn[i],
                                                (i == 0) ? 1 : 0, (i == 3) ? 1 : 0);
        }
    }
}